// round 1
// baseline (speedup 1.0000x reference)
#include <cuda_runtime.h>
#include <math.h>
#include <stdint.h>

#define NT 9
#define NN 50000
#define NE 800000
#define NREL 15
#define DIN 64
#define HH 128

// Relation tables
__device__ __constant__ int c_dst[NREL] = {1,0,2,0,2,3,0,7,4,0,8,4,6,5,0};
__device__ __constant__ float c_invcnt[NT] = {1.f/5.f,1.f,1.f/2.f,1.f,1.f/2.f,1.f,1.f,1.f,1.f};

static const int h_src[NREL] = {0,1,0,2,1,0,3,3,0,4,0,1,0,0,5};
static const int h_dst[NREL] = {1,0,2,0,2,3,0,7,4,0,8,4,6,5,0};

// Scratch (device globals: allocation-free rule)
__device__ float g_xs0[(size_t)NT*NN*HH];   // 230 MB
__device__ float g_xs1[(size_t)NT*NN*HH];   // 230 MB
__device__ float g_acc[(size_t)NT*NN*HH];   // 230 MB
__device__ float g_msg[(size_t)NN*HH];      // 25.6 MB
__device__ int   g_cnt[NREL*NN];
__device__ int   g_off[NREL*(NN+1)];
__device__ int   g_tmp[NREL*NN];
__device__ int   g_csrc[(size_t)NREL*NE];   // 48 MB
__device__ float g_wrc[NT*HH*HH];
__device__ float g_bc[NT*HH];

// ---------------------------------------------------------------------------
// CSR build: counting sort of edges by dst, per relation
// ---------------------------------------------------------------------------
__global__ void k_zero_cnt() {
    int i = blockIdx.x * blockDim.x + threadIdx.x;
    if (i < NREL * NN) g_cnt[i] = 0;
}

__global__ void k_hist(const int* __restrict__ edges) {
    int i = blockIdx.x * blockDim.x + threadIdx.x;
    if (i >= NREL * NE) return;
    int r = i / NE;
    int e = i - r * NE;
    int dst = edges[(size_t)r * 2 * NE + NE + e];
    atomicAdd(&g_cnt[r * NN + dst], 1);
}

__global__ void k_scan() {
    int r = blockIdx.x;
    int t = threadIdx.x;
    __shared__ int s[1024];
    int carry = 0;
    for (int base = 0; base < NN; base += 1024) {
        int i = base + t;
        int v = (i < NN) ? g_cnt[r * NN + i] : 0;
        s[t] = v;
        __syncthreads();
        #pragma unroll
        for (int d = 1; d < 1024; d <<= 1) {
            int x = (t >= d) ? s[t - d] : 0;
            __syncthreads();
            s[t] += x;
            __syncthreads();
        }
        int excl = carry + s[t] - v;
        if (i < NN) {
            g_off[r * (NN + 1) + i] = excl;
            g_tmp[r * NN + i] = excl;
        }
        carry += s[1023];
        __syncthreads();
    }
    if (t == 0) g_off[r * (NN + 1) + NN] = carry;
}

__global__ void k_fill(const int* __restrict__ edges) {
    int i = blockIdx.x * blockDim.x + threadIdx.x;
    if (i >= NREL * NE) return;
    int r = i / NE;
    int e = i - r * NE;
    int src = edges[(size_t)r * 2 * NE + e];
    int dst = edges[(size_t)r * 2 * NE + NE + e];
    int pos = atomicAdd(&g_tmp[r * NN + dst], 1);
    g_csrc[(size_t)r * NE + pos] = src;
}

// ---------------------------------------------------------------------------
// Combine Wr / b across relations sharing a dst type
// ---------------------------------------------------------------------------
template <int K>
__global__ void k_combW(const float* __restrict__ Wr) {
    int idx = blockIdx.x * blockDim.x + threadIdx.x;
    if (idx >= NT * K * HH) return;
    int i = idx / (K * HH);
    int j = idx - i * (K * HH);
    float s = 0.f;
    #pragma unroll
    for (int r = 0; r < NREL; r++)
        if (c_dst[r] == i) s += Wr[(size_t)r * K * HH + j];
    g_wrc[(size_t)i * K * HH + j] = s;
}

__global__ void k_combB(const float* __restrict__ b) {
    int idx = blockIdx.x * blockDim.x + threadIdx.x;
    if (idx >= NT * HH) return;
    int i = idx / HH;
    int j = idx - i * HH;
    float s = 0.f;
    #pragma unroll
    for (int r = 0; r < NREL; r++)
        if (c_dst[r] == i) s += b[r * HH + j];
    g_bc[i * HH + j] = s;
}

// ---------------------------------------------------------------------------
// CSR gather-mean aggregation: one block (D threads) per destination row
// ---------------------------------------------------------------------------
template <int D>
__global__ void k_agg(const float* __restrict__ xs, int r) {
    int row = blockIdx.x;
    int t = threadIdx.x;
    int o0 = g_off[r * (NN + 1) + row];
    int o1 = g_off[r * (NN + 1) + row + 1];
    const int* __restrict__ srcs = g_csrc + (size_t)r * NE;
    float a0 = 0.f, a1 = 0.f, a2 = 0.f, a3 = 0.f;
    int e = o0;
    for (; e + 4 <= o1; e += 4) {
        int s0 = srcs[e], s1 = srcs[e + 1], s2 = srcs[e + 2], s3 = srcs[e + 3];
        a0 += xs[(size_t)s0 * D + t];
        a1 += xs[(size_t)s1 * D + t];
        a2 += xs[(size_t)s2 * D + t];
        a3 += xs[(size_t)s3 * D + t];
    }
    for (; e < o1; e++) a0 += xs[(size_t)srcs[e] * D + t];
    float sum = (a0 + a1) + (a2 + a3);
    float inv = (o1 > o0) ? 1.f / (float)(o1 - o0) : 0.f;
    g_msg[(size_t)row * D + t] = sum * inv;
}

// ---------------------------------------------------------------------------
// SGEMM: C[M,128] (+)= A[M,K] * B[K,128] (+ bias). BM=BN=128, BK=16, 8x8/thread
// ---------------------------------------------------------------------------
template <int K, bool ACCUM, bool BIAS>
__global__ void __launch_bounds__(256) k_gemm(const float* __restrict__ A,
                                              const float* __restrict__ B,
                                              const float* __restrict__ bias,
                                              float* __restrict__ C) {
    const int M = NN;
    __shared__ float As[128][16];
    __shared__ float Bs[16][128];
    int tid = threadIdx.x;
    int tx = tid & 15;       // 0..15  (n dimension)
    int ty = tid >> 4;       // 0..15  (m dimension)
    int r0 = blockIdx.x * 128;

    float acc[8][8];
    #pragma unroll
    for (int i = 0; i < 8; i++)
        #pragma unroll
        for (int j = 0; j < 8; j++) acc[i][j] = 0.f;

    for (int k0 = 0; k0 < K; k0 += 16) {
        // A tile: 128 rows x 16 cols = 512 float4, 2 per thread
        #pragma unroll
        for (int l = 0; l < 2; l++) {
            int f = tid * 2 + l;
            int row = f >> 2, c4 = f & 3;
            int grow = r0 + row;
            float4 v = make_float4(0.f, 0.f, 0.f, 0.f);
            if (grow < M)
                v = *reinterpret_cast<const float4*>(A + (size_t)grow * K + k0 + c4 * 4);
            *reinterpret_cast<float4*>(&As[row][c4 * 4]) = v;
        }
        // B tile: 16 rows x 128 cols = 512 float4, 2 per thread
        #pragma unroll
        for (int l = 0; l < 2; l++) {
            int f = tid * 2 + l;
            int row = f >> 5, c4 = f & 31;
            float4 v = *reinterpret_cast<const float4*>(B + (size_t)(k0 + row) * HH + c4 * 4);
            *reinterpret_cast<float4*>(&Bs[row][c4 * 4]) = v;
        }
        __syncthreads();
        #pragma unroll
        for (int kk = 0; kk < 16; kk++) {
            float a[8];
            #pragma unroll
            for (int i = 0; i < 8; i++) a[i] = As[ty * 8 + i][kk];
            float4 b0 = *reinterpret_cast<const float4*>(&Bs[kk][tx * 8]);
            float4 b1 = *reinterpret_cast<const float4*>(&Bs[kk][tx * 8 + 4]);
            #pragma unroll
            for (int i = 0; i < 8; i++) {
                acc[i][0] += a[i] * b0.x;
                acc[i][1] += a[i] * b0.y;
                acc[i][2] += a[i] * b0.z;
                acc[i][3] += a[i] * b0.w;
                acc[i][4] += a[i] * b1.x;
                acc[i][5] += a[i] * b1.y;
                acc[i][6] += a[i] * b1.z;
                acc[i][7] += a[i] * b1.w;
            }
        }
        __syncthreads();
    }

    #pragma unroll
    for (int i = 0; i < 8; i++) {
        int grow = r0 + ty * 8 + i;
        if (grow >= M) continue;
        float* cp = C + (size_t)grow * HH + tx * 8;
        #pragma unroll
        for (int j = 0; j < 8; j += 4) {
            float4 v;
            v.x = acc[i][j]; v.y = acc[i][j + 1]; v.z = acc[i][j + 2]; v.w = acc[i][j + 3];
            if (BIAS) {
                v.x += bias[tx * 8 + j];
                v.y += bias[tx * 8 + j + 1];
                v.z += bias[tx * 8 + j + 2];
                v.w += bias[tx * 8 + j + 3];
            }
            if (ACCUM) {
                float4 o = *reinterpret_cast<const float4*>(cp + j);
                v.x += o.x; v.y += o.y; v.z += o.z; v.w += o.w;
            }
            *reinterpret_cast<float4*>(cp + j) = v;
        }
    }
}

// ---------------------------------------------------------------------------
// Block-wide sum over 128 threads (result broadcast to all threads)
// ---------------------------------------------------------------------------
__device__ __forceinline__ float blockSum128(float v, float* sh) {
    #pragma unroll
    for (int o = 16; o > 0; o >>= 1) v += __shfl_xor_sync(0xffffffffu, v, o);
    int w = threadIdx.x >> 5;
    if ((threadIdx.x & 31) == 0) sh[w] = v;
    __syncthreads();
    float tot = sh[0] + sh[1] + sh[2] + sh[3];
    __syncthreads();
    return tot;
}

// HeteroConv mean across relations + leaky_relu + LayerNorm
__global__ void k_norm(const float* __restrict__ gam, const float* __restrict__ bet,
                       float* __restrict__ out) {
    __shared__ float sh[4];
    size_t bid = blockIdx.x;
    int t = threadIdx.x;
    int type = (int)(bid / NN);
    float v = g_acc[bid * HH + t] * c_invcnt[type];
    v = (v >= 0.f) ? v : 0.01f * v;
    float mu = blockSum128(v, sh) * (1.f / HH);
    float d = v - mu;
    float var = blockSum128(d * d, sh) * (1.f / HH);
    out[bid * HH + t] = d * rsqrtf(var + 1e-5f) * gam[t] + bet[t];
}

// concat(9 types) @ Wfc + bfc, sigmoid
__global__ void k_final(const float* __restrict__ xs, const float* __restrict__ Wfc,
                        const float* __restrict__ bfc, float* __restrict__ out) {
    __shared__ float sh[4];
    int n = blockIdx.x;
    int t = threadIdx.x;
    float p = 0.f;
    #pragma unroll
    for (int i = 0; i < NT; i++)
        p += xs[((size_t)i * NN + n) * HH + t] * Wfc[i * HH + t];
    float tot = blockSum128(p, sh);
    if (t == 0) out[n] = 1.f / (1.f + expf(-(tot + bfc[0])));
}

// ---------------------------------------------------------------------------
// Host driver
// ---------------------------------------------------------------------------
template <int K>
static void run_layer(const float* xin, const float* Wl, const float* Wr,
                      const float* b, const float* gam, const float* bet,
                      float* p_wrc, float* p_bc, float* p_acc, float* p_msg,
                      float* out) {
    k_combW<K><<<(NT * K * HH + 255) / 256, 256>>>(Wr);
    k_combB<<<(NT * HH + 255) / 256, 256>>>(b);
    // acc[i] = xs[i] @ Wr_comb[i] + b_comb[i]
    for (int i = 0; i < NT; i++)
        k_gemm<K, false, true><<<(NN + 127) / 128, 256>>>(
            xin + (size_t)i * NN * K, p_wrc + (size_t)i * K * HH,
            p_bc + (size_t)i * HH, p_acc + (size_t)i * NN * HH);
    // acc[dst] += mean_agg(xs[src]) @ Wl[r]
    for (int r = 0; r < NREL; r++) {
        k_agg<K><<<NN, K>>>(xin + (size_t)h_src[r] * NN * K, r);
        k_gemm<K, true, false><<<(NN + 127) / 128, 256>>>(
            p_msg, Wl + (size_t)r * K * HH, nullptr,
            p_acc + (size_t)h_dst[r] * NN * HH);
    }
    k_norm<<<NT * NN, HH>>>(gam, bet, out);
}

extern "C" void kernel_launch(void* const* d_in, const int* in_sizes, int n_in,
                              void* d_out, int out_size) {
    const float* x    = (const float*)d_in[0];
    const int* edges  = (const int*)d_in[1];
    const float* Wl1  = (const float*)d_in[2];
    const float* Wr1  = (const float*)d_in[3];
    const float* b1   = (const float*)d_in[4];
    const float* Wl2  = (const float*)d_in[5];
    const float* Wr2  = (const float*)d_in[6];
    const float* b2   = (const float*)d_in[7];
    const float* Wl3  = (const float*)d_in[8];
    const float* Wr3  = (const float*)d_in[9];
    const float* b3   = (const float*)d_in[10];
    const float* g1   = (const float*)d_in[11];
    const float* be1  = (const float*)d_in[12];
    const float* g2   = (const float*)d_in[13];
    const float* be2  = (const float*)d_in[14];
    const float* g3   = (const float*)d_in[15];
    const float* be3  = (const float*)d_in[16];
    const float* Wfc  = (const float*)d_in[17];
    const float* bfc  = (const float*)d_in[18];
    float* out = (float*)d_out;

    float *p_xs0, *p_xs1, *p_acc, *p_msg, *p_wrc, *p_bc;
    cudaGetSymbolAddress((void**)&p_xs0, g_xs0);
    cudaGetSymbolAddress((void**)&p_xs1, g_xs1);
    cudaGetSymbolAddress((void**)&p_acc, g_acc);
    cudaGetSymbolAddress((void**)&p_msg, g_msg);
    cudaGetSymbolAddress((void**)&p_wrc, g_wrc);
    cudaGetSymbolAddress((void**)&p_bc, g_bc);

    // Build CSR (edges -> per-relation dst-sorted adjacency), reused by all 3 layers
    k_zero_cnt<<<(NREL * NN + 255) / 256, 256>>>();
    k_hist<<<(NREL * NE + 255) / 256, 256>>>(edges);
    k_scan<<<NREL, 1024>>>();
    k_fill<<<(NREL * NE + 255) / 256, 256>>>(edges);

    run_layer<DIN>(x,     Wl1, Wr1, b1, g1, be1, p_wrc, p_bc, p_acc, p_msg, p_xs0);
    run_layer<HH> (p_xs0, Wl2, Wr2, b2, g2, be2, p_wrc, p_bc, p_acc, p_msg, p_xs1);
    run_layer<HH> (p_xs1, Wl3, Wr3, b3, g3, be3, p_wrc, p_bc, p_acc, p_msg, p_xs0);

    k_final<<<NN, HH>>>(p_xs0, Wfc, bfc, out);
}

// round 2
// speedup vs baseline: 1.0320x; 1.0320x over previous
#include <cuda_runtime.h>
#include <math.h>
#include <stdint.h>

#define NT 9
#define NN 50000
#define NE 800000
#define NREL 15
#define DIN 64
#define HH 128

// Relation tables
__device__ __constant__ int c_dst[NREL] = {1,0,2,0,2,3,0,7,4,0,8,4,6,5,0};
__device__ __constant__ float c_invcnt[NT] = {1.f/5.f,1.f,1.f/2.f,1.f,1.f/2.f,1.f,1.f,1.f,1.f};

static const int h_src[NREL] = {0,1,0,2,1,0,3,3,0,4,0,1,0,0,5};
static const int h_dst[NREL] = {1,0,2,0,2,3,0,7,4,0,8,4,6,5,0};

// Scratch (device globals: allocation-free rule)
__device__ float g_xs0[(size_t)NT*NN*HH];
__device__ float g_xs1[(size_t)NT*NN*HH];
__device__ float g_acc[(size_t)NT*NN*HH];
__device__ float g_msg[(size_t)NN*HH];
__device__ int   g_cnt[NREL*NN];
__device__ int   g_off[NREL*(NN+1)];
__device__ int   g_tmp[NREL*NN];
__device__ int   g_csrc[(size_t)NREL*NE];
__device__ float g_wrc[NT*HH*HH];
__device__ float g_bc[NT*HH];

// ---------------------------------------------------------------------------
// CSR build
// ---------------------------------------------------------------------------
__global__ void k_zero_cnt() {
    int i = blockIdx.x * blockDim.x + threadIdx.x;
    if (i < NREL * NN) g_cnt[i] = 0;
}

__global__ void k_hist(const int* __restrict__ edges) {
    int i = blockIdx.x * blockDim.x + threadIdx.x;
    if (i >= NREL * NE) return;
    int r = i / NE;
    int e = i - r * NE;
    int dst = edges[(size_t)r * 2 * NE + NE + e];
    atomicAdd(&g_cnt[r * NN + dst], 1);
}

__global__ void k_scan() {
    int r = blockIdx.x;
    int t = threadIdx.x;
    __shared__ int s[1024];
    int carry = 0;
    for (int base = 0; base < NN; base += 1024) {
        int i = base + t;
        int v = (i < NN) ? g_cnt[r * NN + i] : 0;
        s[t] = v;
        __syncthreads();
        #pragma unroll
        for (int d = 1; d < 1024; d <<= 1) {
            int x = (t >= d) ? s[t - d] : 0;
            __syncthreads();
            s[t] += x;
            __syncthreads();
        }
        int excl = carry + s[t] - v;
        if (i < NN) {
            g_off[r * (NN + 1) + i] = excl;
            g_tmp[r * NN + i] = excl;
        }
        carry += s[1023];
        __syncthreads();
    }
    if (t == 0) g_off[r * (NN + 1) + NN] = carry;
}

__global__ void k_fill(const int* __restrict__ edges) {
    int i = blockIdx.x * blockDim.x + threadIdx.x;
    if (i >= NREL * NE) return;
    int r = i / NE;
    int e = i - r * NE;
    int src = edges[(size_t)r * 2 * NE + e];
    int dst = edges[(size_t)r * 2 * NE + NE + e];
    int pos = atomicAdd(&g_tmp[r * NN + dst], 1);
    g_csrc[(size_t)r * NE + pos] = src;
}

// ---------------------------------------------------------------------------
// Combine Wr / b across relations sharing a dst type
// ---------------------------------------------------------------------------
template <int K>
__global__ void k_combW(const float* __restrict__ Wr) {
    int idx = blockIdx.x * blockDim.x + threadIdx.x;
    if (idx >= NT * K * HH) return;
    int i = idx / (K * HH);
    int j = idx - i * (K * HH);
    float s = 0.f;
    #pragma unroll
    for (int r = 0; r < NREL; r++)
        if (c_dst[r] == i) s += Wr[(size_t)r * K * HH + j];
    g_wrc[(size_t)i * K * HH + j] = s;
}

__global__ void k_combB(const float* __restrict__ b) {
    int idx = blockIdx.x * blockDim.x + threadIdx.x;
    if (idx >= NT * HH) return;
    int i = idx / HH;
    int j = idx - i * HH;
    float s = 0.f;
    #pragma unroll
    for (int r = 0; r < NREL; r++)
        if (c_dst[r] == i) s += b[r * HH + j];
    g_bc[i * HH + j] = s;
}

// ---------------------------------------------------------------------------
// CSR gather-mean aggregation: one block (D threads) per destination row
// ---------------------------------------------------------------------------
template <int D>
__global__ void k_agg(const float* __restrict__ xs, int r) {
    int row = blockIdx.x;
    int t = threadIdx.x;
    int o0 = g_off[r * (NN + 1) + row];
    int o1 = g_off[r * (NN + 1) + row + 1];
    const int* __restrict__ srcs = g_csrc + (size_t)r * NE;
    float a0 = 0.f, a1 = 0.f, a2 = 0.f, a3 = 0.f;
    int e = o0;
    for (; e + 4 <= o1; e += 4) {
        int s0 = srcs[e], s1 = srcs[e + 1], s2 = srcs[e + 2], s3 = srcs[e + 3];
        a0 += xs[(size_t)s0 * D + t];
        a1 += xs[(size_t)s1 * D + t];
        a2 += xs[(size_t)s2 * D + t];
        a3 += xs[(size_t)s3 * D + t];
    }
    for (; e < o1; e++) a0 += xs[(size_t)srcs[e] * D + t];
    float sum = (a0 + a1) + (a2 + a3);
    float inv = (o1 > o0) ? 1.f / (float)(o1 - o0) : 0.f;
    g_msg[(size_t)row * D + t] = sum * inv;
}

// ---------------------------------------------------------------------------
// TF32 tensor-core GEMM: C[NN,128] (+)= A[NN,K] * B[K,128] (+bias)
// BM=BN=128, BK=32, 8 warps (2 M x 4 N), warp tile 64x32, mma.m16n8k8.tf32
// SMEM tiles are staged pre-permuted into mma fragment order so the mainloop
// does only vectorized LDS (LDS.128 for A frags, LDS.64 for B frags).
// ---------------------------------------------------------------------------
__device__ __forceinline__ uint32_t f2tf32(float f) {
    uint32_t u;
    asm("cvt.rna.tf32.f32 %0, %1;" : "=r"(u) : "f"(f));
    return u;
}

__device__ __forceinline__ void mma_tf32(float* d, const uint32_t* a, const uint32_t* b) {
    asm volatile(
        "mma.sync.aligned.m16n8k8.row.col.f32.tf32.tf32.f32 "
        "{%0,%1,%2,%3}, {%4,%5,%6,%7}, {%8,%9}, {%0,%1,%2,%3};"
        : "+f"(d[0]), "+f"(d[1]), "+f"(d[2]), "+f"(d[3])
        : "r"(a[0]), "r"(a[1]), "r"(a[2]), "r"(a[3]), "r"(b[0]), "r"(b[1]));
}

template <int K, bool ACCUM, bool BIAS>
__global__ void __launch_bounds__(256) k_gemm_tc(const float* __restrict__ A,
                                                const float* __restrict__ B,
                                                const float* __restrict__ bias,
                                                float* __restrict__ C) {
    // A fragments: [mt(8)][kt(4)][lane(32)][j(4)]  (j = a0..a3)
    // B fragments: [kt(4)][nt(16)][lane(32)][breg(2)]
    __shared__ uint32_t sA[8 * 4 * 32 * 4];
    __shared__ uint32_t sB[4 * 16 * 32 * 2];

    int tid = threadIdx.x;
    int lane = tid & 31;
    int warp = tid >> 5;
    int wm = warp >> 2;          // 0..1
    int wn = warp & 3;           // 0..3
    int r0 = blockIdx.x * 128;

    float acc[4][4][4];
    #pragma unroll
    for (int mt = 0; mt < 4; mt++)
        #pragma unroll
        for (int nt = 0; nt < 4; nt++)
            #pragma unroll
            for (int j = 0; j < 4; j++) acc[mt][nt][j] = 0.f;

    for (int k0 = 0; k0 < K; k0 += 32) {
        __syncthreads();
        // ---- stage A tile (128 x 32) into fragment order ----
        #pragma unroll
        for (int l = 0; l < 4; l++) {
            int f = tid + l * 256;          // 0..1023 float4s
            int row = f >> 3;               // 0..127
            int c0 = (f & 7) * 4;           // 0,4,...,28
            float4 v = make_float4(0.f, 0.f, 0.f, 0.f);
            if (r0 + row < NN)
                v = *reinterpret_cast<const float4*>(A + (size_t)(r0 + row) * K + k0 + c0);
            int mt = row >> 4;
            int r16 = row & 15;
            int kt = c0 >> 3;
            int jb = ((r16 >> 3) & 1) + (((c0 & 7) >= 4) ? 2 : 0);
            int lanebase = (r16 & 7) * 4;
            uint32_t* dst = &sA[((mt * 4 + kt) * 32) * 4 + jb];
            dst[(lanebase + 0) * 4] = f2tf32(v.x);
            dst[(lanebase + 1) * 4] = f2tf32(v.y);
            dst[(lanebase + 2) * 4] = f2tf32(v.z);
            dst[(lanebase + 3) * 4] = f2tf32(v.w);
        }
        // ---- stage B tile (32 x 128) into fragment order ----
        #pragma unroll
        for (int l = 0; l < 4; l++) {
            int f = tid + l * 256;          // 0..1023 float4s
            int krow = f >> 5;              // 0..31
            int n0 = (f & 31) * 4;          // 0,4,...,124
            float4 v = *reinterpret_cast<const float4*>(B + (size_t)(k0 + krow) * HH + n0);
            int kt = krow >> 3;
            int k8 = krow & 7;
            int breg = k8 >> 2;
            int lanek = k8 & 3;
            int nt = n0 >> 3;
            int nbase = n0 & 7;             // 0 or 4
            uint32_t* dst = &sB[((kt * 16 + nt) * 32) * 2 + breg];
            dst[((nbase + 0) * 4 + lanek) * 2] = f2tf32(v.x);
            dst[((nbase + 1) * 4 + lanek) * 2] = f2tf32(v.y);
            dst[((nbase + 2) * 4 + lanek) * 2] = f2tf32(v.z);
            dst[((nbase + 3) * 4 + lanek) * 2] = f2tf32(v.w);
        }
        __syncthreads();
        // ---- mainloop: 4 k-steps of k=8 ----
        #pragma unroll
        for (int kt = 0; kt < 4; kt++) {
            uint32_t af[4][4];
            uint32_t bf[4][2];
            #pragma unroll
            for (int mt = 0; mt < 4; mt++) {
                uint4 t = *reinterpret_cast<const uint4*>(
                    &sA[(((wm * 4 + mt) * 4 + kt) * 32 + lane) * 4]);
                af[mt][0] = t.x; af[mt][1] = t.y; af[mt][2] = t.z; af[mt][3] = t.w;
            }
            #pragma unroll
            for (int nt = 0; nt < 4; nt++) {
                uint2 t = *reinterpret_cast<const uint2*>(
                    &sB[((kt * 16 + wn * 4 + nt) * 32 + lane) * 2]);
                bf[nt][0] = t.x; bf[nt][1] = t.y;
            }
            #pragma unroll
            for (int mt = 0; mt < 4; mt++)
                #pragma unroll
                for (int nt = 0; nt < 4; nt++)
                    mma_tf32(acc[mt][nt], af[mt], bf[nt]);
        }
    }

    // ---- epilogue ----
    #pragma unroll
    for (int mt = 0; mt < 4; mt++) {
        #pragma unroll
        for (int nt = 0; nt < 4; nt++) {
            int row = r0 + wm * 64 + mt * 16 + (lane >> 2);
            int col = wn * 32 + nt * 8 + (lane & 3) * 2;
            float b0 = 0.f, b1 = 0.f;
            if (BIAS) { b0 = bias[col]; b1 = bias[col + 1]; }
            if (row < NN) {
                float* cp = C + (size_t)row * HH + col;
                float2 v = make_float2(acc[mt][nt][0] + b0, acc[mt][nt][1] + b1);
                if (ACCUM) {
                    float2 o = *reinterpret_cast<const float2*>(cp);
                    v.x += o.x; v.y += o.y;
                }
                *reinterpret_cast<float2*>(cp) = v;
            }
            if (row + 8 < NN) {
                float* cp = C + (size_t)(row + 8) * HH + col;
                float2 v = make_float2(acc[mt][nt][2] + b0, acc[mt][nt][3] + b1);
                if (ACCUM) {
                    float2 o = *reinterpret_cast<const float2*>(cp);
                    v.x += o.x; v.y += o.y;
                }
                *reinterpret_cast<float2*>(cp) = v;
            }
        }
    }
}

// ---------------------------------------------------------------------------
// Block-wide sum over 128 threads
// ---------------------------------------------------------------------------
__device__ __forceinline__ float blockSum128(float v, float* sh) {
    #pragma unroll
    for (int o = 16; o > 0; o >>= 1) v += __shfl_xor_sync(0xffffffffu, v, o);
    int w = threadIdx.x >> 5;
    if ((threadIdx.x & 31) == 0) sh[w] = v;
    __syncthreads();
    float tot = sh[0] + sh[1] + sh[2] + sh[3];
    __syncthreads();
    return tot;
}

__global__ void k_norm(const float* __restrict__ gam, const float* __restrict__ bet,
                       float* __restrict__ out) {
    __shared__ float sh[4];
    size_t bid = blockIdx.x;
    int t = threadIdx.x;
    int type = (int)(bid / NN);
    float v = g_acc[bid * HH + t] * c_invcnt[type];
    v = (v >= 0.f) ? v : 0.01f * v;
    float mu = blockSum128(v, sh) * (1.f / HH);
    float d = v - mu;
    float var = blockSum128(d * d, sh) * (1.f / HH);
    out[bid * HH + t] = d * rsqrtf(var + 1e-5f) * gam[t] + bet[t];
}

__global__ void k_final(const float* __restrict__ xs, const float* __restrict__ Wfc,
                        const float* __restrict__ bfc, float* __restrict__ out) {
    __shared__ float sh[4];
    int n = blockIdx.x;
    int t = threadIdx.x;
    float p = 0.f;
    #pragma unroll
    for (int i = 0; i < NT; i++)
        p += xs[((size_t)i * NN + n) * HH + t] * Wfc[i * HH + t];
    float tot = blockSum128(p, sh);
    if (t == 0) out[n] = 1.f / (1.f + expf(-(tot + bfc[0])));
}

// ---------------------------------------------------------------------------
// Host driver
// ---------------------------------------------------------------------------
template <int K>
static void run_layer(const float* xin, const float* Wl, const float* Wr,
                      const float* b, const float* gam, const float* bet,
                      float* p_wrc, float* p_bc, float* p_acc, float* p_msg,
                      float* out) {
    k_combW<K><<<(NT * K * HH + 255) / 256, 256>>>(Wr);
    k_combB<<<(NT * HH + 255) / 256, 256>>>(b);
    for (int i = 0; i < NT; i++)
        k_gemm_tc<K, false, true><<<(NN + 127) / 128, 256>>>(
            xin + (size_t)i * NN * K, p_wrc + (size_t)i * K * HH,
            p_bc + (size_t)i * HH, p_acc + (size_t)i * NN * HH);
    for (int r = 0; r < NREL; r++) {
        k_agg<K><<<NN, K>>>(xin + (size_t)h_src[r] * NN * K, r);
        k_gemm_tc<K, true, false><<<(NN + 127) / 128, 256>>>(
            p_msg, Wl + (size_t)r * K * HH, nullptr,
            p_acc + (size_t)h_dst[r] * NN * HH);
    }
    k_norm<<<NT * NN, HH>>>(gam, bet, out);
}

extern "C" void kernel_launch(void* const* d_in, const int* in_sizes, int n_in,
                              void* d_out, int out_size) {
    const float* x    = (const float*)d_in[0];
    const int* edges  = (const int*)d_in[1];
    const float* Wl1  = (const float*)d_in[2];
    const float* Wr1  = (const float*)d_in[3];
    const float* b1   = (const float*)d_in[4];
    const float* Wl2  = (const float*)d_in[5];
    const float* Wr2  = (const float*)d_in[6];
    const float* b2   = (const float*)d_in[7];
    const float* Wl3  = (const float*)d_in[8];
    const float* Wr3  = (const float*)d_in[9];
    const float* b3   = (const float*)d_in[10];
    const float* g1   = (const float*)d_in[11];
    const float* be1  = (const float*)d_in[12];
    const float* g2   = (const float*)d_in[13];
    const float* be2  = (const float*)d_in[14];
    const float* g3   = (const float*)d_in[15];
    const float* be3  = (const float*)d_in[16];
    const float* Wfc  = (const float*)d_in[17];
    const float* bfc  = (const float*)d_in[18];
    float* out = (float*)d_out;

    float *p_xs0, *p_xs1, *p_acc, *p_msg, *p_wrc, *p_bc;
    cudaGetSymbolAddress((void**)&p_xs0, g_xs0);
    cudaGetSymbolAddress((void**)&p_xs1, g_xs1);
    cudaGetSymbolAddress((void**)&p_acc, g_acc);
    cudaGetSymbolAddress((void**)&p_msg, g_msg);
    cudaGetSymbolAddress((void**)&p_wrc, g_wrc);
    cudaGetSymbolAddress((void**)&p_bc, g_bc);

    k_zero_cnt<<<(NREL * NN + 255) / 256, 256>>>();
    k_hist<<<(NREL * NE + 255) / 256, 256>>>(edges);
    k_scan<<<NREL, 1024>>>();
    k_fill<<<(NREL * NE + 255) / 256, 256>>>(edges);

    run_layer<DIN>(x,     Wl1, Wr1, b1, g1, be1, p_wrc, p_bc, p_acc, p_msg, p_xs0);
    run_layer<HH> (p_xs0, Wl2, Wr2, b2, g2, be2, p_wrc, p_bc, p_acc, p_msg, p_xs1);
    run_layer<HH> (p_xs1, Wl3, Wr3, b3, g3, be3, p_wrc, p_bc, p_acc, p_msg, p_xs0);

    k_final<<<NN, HH>>>(p_xs0, Wfc, bfc, out);
}

// round 3
// speedup vs baseline: 1.3543x; 1.3124x over previous
#include <cuda_runtime.h>
#include <math.h>
#include <stdint.h>

#define NT 9
#define NN 50000
#define NE 800000
#define NREL 15
#define DIN 64
#define HH 128

__device__ __constant__ int   c_src[NREL]   = {0,1,0,2,1,0,3,3,0,4,0,1,0,0,5};
__device__ __constant__ int   c_dst[NREL]   = {1,0,2,0,2,3,0,7,4,0,8,4,6,5,0};
__device__ __constant__ float c_invcnt[NT]  = {1.f/5.f,1.f,1.f/2.f,1.f,1.f/2.f,1.f,1.f,1.f,1.f};
__device__ __constant__ int   c_nseg[NT]    = {6,2,3,2,3,2,2,2,2};
// segment 0 = self (Wrc); others = relation ids with dst == type
__device__ __constant__ int   c_segrel[NT][6] = {
    {-1,1,3,6,9,14},{-1,0,0,0,0,0},{-1,2,4,0,0,0},{-1,5,0,0,0,0},
    {-1,8,11,0,0,0},{-1,13,0,0,0,0},{-1,12,0,0,0,0},{-1,7,0,0,0,0},{-1,10,0,0,0,0}};

// Scratch (device globals: allocation-free rule)
__device__ float g_xs0[(size_t)NT*NN*HH];
__device__ float g_xs1[(size_t)NT*NN*HH];
__device__ float g_msgs[(size_t)NREL*NN*HH];   // per-relation aggregated messages
__device__ int   g_cnt[NREL*NN];
__device__ int   g_off[NREL*(NN+1)];
__device__ int   g_tmp[NREL*NN];
__device__ int   g_csrc[(size_t)NREL*NE];
__device__ float g_wrc[NT*HH*HH];
__device__ float g_bc[NT*HH];

// ---------------------------------------------------------------------------
// CSR build
// ---------------------------------------------------------------------------
__global__ void k_zero_cnt() {
    int i = blockIdx.x * blockDim.x + threadIdx.x;
    if (i < NREL * NN) g_cnt[i] = 0;
}

__global__ void k_hist(const int* __restrict__ edges) {
    int i = blockIdx.x * blockDim.x + threadIdx.x;
    if (i >= NREL * NE) return;
    int r = i / NE;
    int e = i - r * NE;
    int dst = edges[(size_t)r * 2 * NE + NE + e];
    atomicAdd(&g_cnt[r * NN + dst], 1);
}

__global__ void k_scan() {
    int r = blockIdx.x;
    int t = threadIdx.x;
    __shared__ int s[1024];
    int carry = 0;
    for (int base = 0; base < NN; base += 1024) {
        int i = base + t;
        int v = (i < NN) ? g_cnt[r * NN + i] : 0;
        s[t] = v;
        __syncthreads();
        #pragma unroll
        for (int d = 1; d < 1024; d <<= 1) {
            int x = (t >= d) ? s[t - d] : 0;
            __syncthreads();
            s[t] += x;
            __syncthreads();
        }
        int excl = carry + s[t] - v;
        if (i < NN) {
            g_off[r * (NN + 1) + i] = excl;
            g_tmp[r * NN + i] = excl;
        }
        carry += s[1023];
        __syncthreads();
    }
    if (t == 0) g_off[r * (NN + 1) + NN] = carry;
}

__global__ void k_fill(const int* __restrict__ edges) {
    int i = blockIdx.x * blockDim.x + threadIdx.x;
    if (i >= NREL * NE) return;
    int r = i / NE;
    int e = i - r * NE;
    int src = edges[(size_t)r * 2 * NE + e];
    int dst = edges[(size_t)r * 2 * NE + NE + e];
    int pos = atomicAdd(&g_tmp[r * NN + dst], 1);
    g_csrc[(size_t)r * NE + pos] = src;
}

// ---------------------------------------------------------------------------
// Combine Wr / b across relations sharing a dst type
// ---------------------------------------------------------------------------
template <int K>
__global__ void k_combW(const float* __restrict__ Wr) {
    int idx = blockIdx.x * blockDim.x + threadIdx.x;
    if (idx >= NT * K * HH) return;
    int i = idx / (K * HH);
    int j = idx - i * (K * HH);
    float s = 0.f;
    #pragma unroll
    for (int r = 0; r < NREL; r++)
        if (c_dst[r] == i) s += Wr[(size_t)r * K * HH + j];
    g_wrc[(size_t)i * K * HH + j] = s;
}

__global__ void k_combB(const float* __restrict__ b) {
    int idx = blockIdx.x * blockDim.x + threadIdx.x;
    if (idx >= NT * HH) return;
    int i = idx / HH;
    int j = idx - i * HH;
    float s = 0.f;
    #pragma unroll
    for (int r = 0; r < NREL; r++)
        if (c_dst[r] == i) s += b[r * HH + j];
    g_bc[i * HH + j] = s;
}

// ---------------------------------------------------------------------------
// Aggregation, all relations in one launch: grid (NN, NREL), block D threads
// ---------------------------------------------------------------------------
template <int D>
__global__ void k_agg_all(const float* __restrict__ xs) {
    int r = blockIdx.y;
    int row = blockIdx.x;
    int t = threadIdx.x;
    const float* __restrict__ xsrc = xs + (size_t)c_src[r] * NN * D;
    int o0 = g_off[r * (NN + 1) + row];
    int o1 = g_off[r * (NN + 1) + row + 1];
    const int* __restrict__ srcs = g_csrc + (size_t)r * NE;
    float a0 = 0.f, a1 = 0.f, a2 = 0.f, a3 = 0.f;
    int e = o0;
    for (; e + 4 <= o1; e += 4) {
        int s0 = srcs[e], s1 = srcs[e + 1], s2 = srcs[e + 2], s3 = srcs[e + 3];
        a0 += xsrc[(size_t)s0 * D + t];
        a1 += xsrc[(size_t)s1 * D + t];
        a2 += xsrc[(size_t)s2 * D + t];
        a3 += xsrc[(size_t)s3 * D + t];
    }
    for (; e < o1; e++) a0 += xsrc[(size_t)srcs[e] * D + t];
    float sum = (a0 + a1) + (a2 + a3);
    float inv = (o1 > o0) ? 1.f / (float)(o1 - o0) : 0.f;
    g_msgs[(size_t)r * NN * D + (size_t)row * D + t] = sum * inv;
}

// ---------------------------------------------------------------------------
// Segmented TF32 GEMM with fused leaky-ReLU + LayerNorm epilogue.
// out[type][row, 0:128] = LN(leaky( (concat_seg A_seg) @ (concat_seg B_seg)
//                                   + bc[type]) * invcnt[type] ))
// BM=128, BN=128, BK=32, 8 warps; warp tile = 16 rows x 128 cols so each
// output row lives in 4 lanes of one warp (LN = 2 shfls, no smem).
// ---------------------------------------------------------------------------
__device__ __forceinline__ uint32_t f2tf32(float f) {
    uint32_t u;
    asm("cvt.rna.tf32.f32 %0, %1;" : "=r"(u) : "f"(f));
    return u;
}

__device__ __forceinline__ void mma_tf32(float* d, const uint32_t* a, const uint32_t* b) {
    asm volatile(
        "mma.sync.aligned.m16n8k8.row.col.f32.tf32.tf32.f32 "
        "{%0,%1,%2,%3}, {%4,%5,%6,%7}, {%8,%9}, {%0,%1,%2,%3};"
        : "+f"(d[0]), "+f"(d[1]), "+f"(d[2]), "+f"(d[3])
        : "r"(a[0]), "r"(a[1]), "r"(a[2]), "r"(a[3]), "r"(b[0]), "r"(b[1]));
}

template <int SEGK>
__global__ void __launch_bounds__(256) k_gemm_ln(const float* __restrict__ xin,
                                                const float* __restrict__ Wl,
                                                const float* __restrict__ gam,
                                                const float* __restrict__ bet,
                                                float* __restrict__ out) {
    // A fragments: [m16(8)][kt(4)][lane(32)][j(4)]
    // B fragments: [kt(4)][nt(16)][lane(32)][breg(2)]
    __shared__ uint32_t sA[8 * 4 * 32 * 4];
    __shared__ uint32_t sB[4 * 16 * 32 * 2];

    int tid = threadIdx.x;
    int lane = tid & 31;
    int w = tid >> 5;                 // warp 0..7 -> rows w*16..w*16+15
    int type = blockIdx.y;
    int r0 = blockIdx.x * 128;

    float acc[16][4];
    #pragma unroll
    for (int nt = 0; nt < 16; nt++)
        #pragma unroll
        for (int j = 0; j < 4; j++) acc[nt][j] = 0.f;

    int nseg = c_nseg[type];
    for (int seg = 0; seg < nseg; seg++) {
        int rel = c_segrel[type][seg];
        const float* Abase = (seg == 0) ? xin + (size_t)type * NN * SEGK
                                        : g_msgs + (size_t)rel * NN * SEGK;
        const float* Bbase = (seg == 0) ? g_wrc + (size_t)type * SEGK * HH
                                        : Wl + (size_t)rel * SEGK * HH;
        #pragma unroll
        for (int off = 0; off < SEGK; off += 32) {
            __syncthreads();
            // stage A tile (128 x 32) into fragment order
            #pragma unroll
            for (int l = 0; l < 4; l++) {
                int f = tid + l * 256;          // 0..1023 float4s
                int row = f >> 3;               // 0..127
                int c0 = (f & 7) * 4;           // 0..28
                float4 v = make_float4(0.f, 0.f, 0.f, 0.f);
                if (r0 + row < NN)
                    v = *reinterpret_cast<const float4*>(
                        Abase + (size_t)(r0 + row) * SEGK + off + c0);
                int m16 = row >> 4;
                int r16 = row & 15;
                int kt = c0 >> 3;
                int jb = ((r16 >> 3) & 1) + ((c0 & 4) ? 2 : 0);
                int lanebase = (r16 & 7) * 4;
                uint32_t* dst = &sA[((m16 * 4 + kt) * 32) * 4 + jb];
                dst[(lanebase + 0) * 4] = f2tf32(v.x);
                dst[(lanebase + 1) * 4] = f2tf32(v.y);
                dst[(lanebase + 2) * 4] = f2tf32(v.z);
                dst[(lanebase + 3) * 4] = f2tf32(v.w);
            }
            // stage B tile (32 x 128) into fragment order
            #pragma unroll
            for (int l = 0; l < 4; l++) {
                int f = tid + l * 256;
                int krow = f >> 5;              // 0..31
                int n0 = (f & 31) * 4;          // 0..124
                float4 v = *reinterpret_cast<const float4*>(
                    Bbase + (size_t)(off + krow) * HH + n0);
                int kt = krow >> 3;
                int k8 = krow & 7;
                int breg = k8 >> 2;
                int lanek = k8 & 3;
                int nt = n0 >> 3;
                int nbase = n0 & 7;
                uint32_t* dst = &sB[((kt * 16 + nt) * 32) * 2 + breg];
                dst[((nbase + 0) * 4 + lanek) * 2] = f2tf32(v.x);
                dst[((nbase + 1) * 4 + lanek) * 2] = f2tf32(v.y);
                dst[((nbase + 2) * 4 + lanek) * 2] = f2tf32(v.z);
                dst[((nbase + 3) * 4 + lanek) * 2] = f2tf32(v.w);
            }
            __syncthreads();
            #pragma unroll
            for (int kt = 0; kt < 4; kt++) {
                uint32_t af[4];
                uint4 ta = *reinterpret_cast<const uint4*>(
                    &sA[((w * 4 + kt) * 32 + lane) * 4]);
                af[0] = ta.x; af[1] = ta.y; af[2] = ta.z; af[3] = ta.w;
                #pragma unroll
                for (int nt = 0; nt < 16; nt++) {
                    uint2 tb = *reinterpret_cast<const uint2*>(
                        &sB[((kt * 16 + nt) * 32 + lane) * 2]);
                    uint32_t bf[2] = {tb.x, tb.y};
                    mma_tf32(acc[nt], af, bf);
                }
            }
        }
    }

    // ---- fused epilogue: bias, mean over relations, leaky ReLU, LayerNorm ----
    float inv = c_invcnt[type];
    #pragma unroll
    for (int h = 0; h < 2; h++) {
        int row = r0 + w * 16 + (lane >> 2) + h * 8;
        // value transform
        float v[16][2];
        float s = 0.f;
        #pragma unroll
        for (int nt = 0; nt < 16; nt++) {
            int col = nt * 8 + (lane & 3) * 2;
            float x0 = (acc[nt][2 * h] + g_bc[type * HH + col]) * inv;
            float x1 = (acc[nt][2 * h + 1] + g_bc[type * HH + col + 1]) * inv;
            x0 = (x0 >= 0.f) ? x0 : 0.01f * x0;
            x1 = (x1 >= 0.f) ? x1 : 0.01f * x1;
            v[nt][0] = x0; v[nt][1] = x1;
            s += x0 + x1;
        }
        s += __shfl_xor_sync(0xffffffffu, s, 1);
        s += __shfl_xor_sync(0xffffffffu, s, 2);
        float mu = s * (1.f / HH);
        float q = 0.f;
        #pragma unroll
        for (int nt = 0; nt < 16; nt++) {
            float d0 = v[nt][0] - mu, d1 = v[nt][1] - mu;
            v[nt][0] = d0; v[nt][1] = d1;
            q += d0 * d0 + d1 * d1;
        }
        q += __shfl_xor_sync(0xffffffffu, q, 1);
        q += __shfl_xor_sync(0xffffffffu, q, 2);
        float rs = rsqrtf(q * (1.f / HH) + 1e-5f);
        if (row < NN) {
            float* op = out + (size_t)type * NN * HH + (size_t)row * HH;
            #pragma unroll
            for (int nt = 0; nt < 16; nt++) {
                int col = nt * 8 + (lane & 3) * 2;
                float2 o;
                o.x = v[nt][0] * rs * gam[col] + bet[col];
                o.y = v[nt][1] * rs * gam[col + 1] + bet[col + 1];
                *reinterpret_cast<float2*>(op + col) = o;
            }
        }
    }
}

// ---------------------------------------------------------------------------
// Final: concat(9 types) @ Wfc + bfc, sigmoid
// ---------------------------------------------------------------------------
__device__ __forceinline__ float blockSum128(float v, float* sh) {
    #pragma unroll
    for (int o = 16; o > 0; o >>= 1) v += __shfl_xor_sync(0xffffffffu, v, o);
    int w = threadIdx.x >> 5;
    if ((threadIdx.x & 31) == 0) sh[w] = v;
    __syncthreads();
    float tot = sh[0] + sh[1] + sh[2] + sh[3];
    __syncthreads();
    return tot;
}

__global__ void k_final(const float* __restrict__ xs, const float* __restrict__ Wfc,
                        const float* __restrict__ bfc, float* __restrict__ out) {
    __shared__ float sh[4];
    int n = blockIdx.x;
    int t = threadIdx.x;
    float p = 0.f;
    #pragma unroll
    for (int i = 0; i < NT; i++)
        p += xs[((size_t)i * NN + n) * HH + t] * Wfc[i * HH + t];
    float tot = blockSum128(p, sh);
    if (t == 0) out[n] = 1.f / (1.f + expf(-(tot + bfc[0])));
}

// ---------------------------------------------------------------------------
// Host driver
// ---------------------------------------------------------------------------
template <int SEGK>
static void run_layer(const float* xin, const float* Wl, const float* Wr,
                      const float* b, const float* gam, const float* bet,
                      float* out) {
    k_combW<SEGK><<<(NT * SEGK * HH + 255) / 256, 256>>>(Wr);
    k_combB<<<(NT * HH + 255) / 256, 256>>>(b);
    dim3 ga(NN, NREL);
    k_agg_all<SEGK><<<ga, SEGK>>>(xin);
    dim3 gg((NN + 127) / 128, NT);
    k_gemm_ln<SEGK><<<gg, 256>>>(xin, Wl, gam, bet, out);
}

extern "C" void kernel_launch(void* const* d_in, const int* in_sizes, int n_in,
                              void* d_out, int out_size) {
    const float* x    = (const float*)d_in[0];
    const int* edges  = (const int*)d_in[1];
    const float* Wl1  = (const float*)d_in[2];
    const float* Wr1  = (const float*)d_in[3];
    const float* b1   = (const float*)d_in[4];
    const float* Wl2  = (const float*)d_in[5];
    const float* Wr2  = (const float*)d_in[6];
    const float* b2   = (const float*)d_in[7];
    const float* Wl3  = (const float*)d_in[8];
    const float* Wr3  = (const float*)d_in[9];
    const float* b3   = (const float*)d_in[10];
    const float* g1   = (const float*)d_in[11];
    const float* be1  = (const float*)d_in[12];
    const float* g2   = (const float*)d_in[13];
    const float* be2  = (const float*)d_in[14];
    const float* g3   = (const float*)d_in[15];
    const float* be3  = (const float*)d_in[16];
    const float* Wfc  = (const float*)d_in[17];
    const float* bfc  = (const float*)d_in[18];
    float* out = (float*)d_out;

    float *p_xs0, *p_xs1;
    cudaGetSymbolAddress((void**)&p_xs0, g_xs0);
    cudaGetSymbolAddress((void**)&p_xs1, g_xs1);

    k_zero_cnt<<<(NREL * NN + 255) / 256, 256>>>();
    k_hist<<<(NREL * NE + 255) / 256, 256>>>(edges);
    k_scan<<<NREL, 1024>>>();
    k_fill<<<(NREL * NE + 255) / 256, 256>>>(edges);

    run_layer<DIN>(x,     Wl1, Wr1, b1, g1, be1, p_xs0);
    run_layer<HH> (p_xs0, Wl2, Wr2, b2, g2, be2, p_xs1);
    run_layer<HH> (p_xs1, Wl3, Wr3, b3, g3, be3, p_xs0);

    k_final<<<NN, HH>>>(p_xs0, Wfc, bfc, out);
}

// round 4
// speedup vs baseline: 2.3394x; 1.7274x over previous
#include <cuda_runtime.h>
#include <cuda_bf16.h>
#include <math.h>
#include <stdint.h>

#define NT 9
#define NN 50000
#define NE 800000
#define NREL 15
#define DIN 64
#define HH 128

__device__ __constant__ int   c_src[NREL]   = {0,1,0,2,1,0,3,3,0,4,0,1,0,0,5};
__device__ __constant__ int   c_dst[NREL]   = {1,0,2,0,2,3,0,7,4,0,8,4,6,5,0};
__device__ __constant__ float c_invcnt[NT]  = {1.f/5.f,1.f,1.f/2.f,1.f,1.f/2.f,1.f,1.f,1.f,1.f};
__device__ __constant__ int   c_nseg[NT]    = {6,2,3,2,3,2,2,2,2};
// segment 0 = self (Wrc); others = relation ids with dst == type
__device__ __constant__ int   c_segrel[NT][6] = {
    {-1,1,3,6,9,14},{-1,0,0,0,0,0},{-1,2,4,0,0,0},{-1,5,0,0,0,0},
    {-1,8,11,0,0,0},{-1,13,0,0,0,0},{-1,12,0,0,0,0},{-1,7,0,0,0,0},{-1,10,0,0,0,0}};

// Scratch (device globals: allocation-free rule)
__device__ float g_xs0[(size_t)NT*NN*HH];
__device__ float g_xs1[(size_t)NT*NN*HH];
__device__ __nv_bfloat16 g_xbf[(size_t)NT*NN*HH];   // bf16 shadow for gathering
__device__ float g_msgs[(size_t)NREL*NN*HH];
__device__ int   g_cnt[NREL*NN];
__device__ int   g_off[NREL*(NN+1)];
__device__ int   g_tmp[NREL*NN];
__device__ int   g_csrc[(size_t)NREL*NE];
__device__ float g_wrc[NT*HH*HH];
__device__ float g_bc[NT*HH];

// ---------------------------------------------------------------------------
// zero counters + convert input x to bf16 shadow (fused)
// ---------------------------------------------------------------------------
__global__ void k_cvt_zero(const float* __restrict__ x) {
    int i = blockIdx.x * blockDim.x + threadIdx.x;
    if (i < NREL * NN) g_cnt[i] = 0;
    if (i < NT * NN * DIN / 2) {
        float2 v = reinterpret_cast<const float2*>(x)[i];
        reinterpret_cast<__nv_bfloat162*>(g_xbf)[i] = __floats2bfloat162_rn(v.x, v.y);
    }
}

__global__ void k_hist(const int* __restrict__ edges) {
    int i = blockIdx.x * blockDim.x + threadIdx.x;
    if (i >= NREL * NE) return;
    int r = i / NE;
    int e = i - r * NE;
    int dst = edges[(size_t)r * 2 * NE + NE + e];
    atomicAdd(&g_cnt[r * NN + dst], 1);
}

__global__ void k_scan() {
    int r = blockIdx.x;
    int t = threadIdx.x;
    __shared__ int s[1024];
    int carry = 0;
    for (int base = 0; base < NN; base += 1024) {
        int i = base + t;
        int v = (i < NN) ? g_cnt[r * NN + i] : 0;
        s[t] = v;
        __syncthreads();
        #pragma unroll
        for (int d = 1; d < 1024; d <<= 1) {
            int x = (t >= d) ? s[t - d] : 0;
            __syncthreads();
            s[t] += x;
            __syncthreads();
        }
        int excl = carry + s[t] - v;
        if (i < NN) {
            g_off[r * (NN + 1) + i] = excl;
            g_tmp[r * NN + i] = excl;
        }
        carry += s[1023];
        __syncthreads();
    }
    if (t == 0) g_off[r * (NN + 1) + NN] = carry;
}

__global__ void k_fill(const int* __restrict__ edges) {
    int i = blockIdx.x * blockDim.x + threadIdx.x;
    if (i >= NREL * NE) return;
    int r = i / NE;
    int e = i - r * NE;
    int src = edges[(size_t)r * 2 * NE + e];
    int dst = edges[(size_t)r * 2 * NE + NE + e];
    int pos = atomicAdd(&g_tmp[r * NN + dst], 1);
    g_csrc[(size_t)r * NE + pos] = src;
}

// ---------------------------------------------------------------------------
// Combine Wr / b across relations sharing a dst type
// ---------------------------------------------------------------------------
template <int K>
__global__ void k_combW(const float* __restrict__ Wr) {
    int idx = blockIdx.x * blockDim.x + threadIdx.x;
    if (idx >= NT * K * HH) return;
    int i = idx / (K * HH);
    int j = idx - i * (K * HH);
    float s = 0.f;
    #pragma unroll
    for (int r = 0; r < NREL; r++)
        if (c_dst[r] == i) s += Wr[(size_t)r * K * HH + j];
    g_wrc[(size_t)i * K * HH + j] = s;
}

__global__ void k_combB(const float* __restrict__ b) {
    int idx = blockIdx.x * blockDim.x + threadIdx.x;
    if (idx >= NT * HH) return;
    int i = idx / HH;
    int j = idx - i * HH;
    float s = 0.f;
    #pragma unroll
    for (int r = 0; r < NREL; r++)
        if (c_dst[r] == i) s += b[r * HH + j];
    g_bc[i * HH + j] = s;
}

// ---------------------------------------------------------------------------
// bf16 gather aggregation. Block = 128 threads covering (256/D) rows,
// D/2 threads per row, each handling one bf16x2 pair. fp32 accumulate,
// fp32 message output.
// ---------------------------------------------------------------------------
template <int D>
__global__ void k_agg_bf() {
    constexpr int TPR = D / 2;                 // threads per row
    int r = blockIdx.y;
    int row = blockIdx.x * (128 / TPR) + threadIdx.y;
    int t = threadIdx.x;
    const __nv_bfloat16* __restrict__ xsrc = g_xbf + (size_t)c_src[r] * NN * D;
    int o0 = g_off[r * (NN + 1) + row];
    int o1 = g_off[r * (NN + 1) + row + 1];
    const int* __restrict__ srcs = g_csrc + (size_t)r * NE;
    float ax0 = 0.f, ay0 = 0.f, ax1 = 0.f, ay1 = 0.f;
    float ax2 = 0.f, ay2 = 0.f, ax3 = 0.f, ay3 = 0.f;
    int e = o0;
    for (; e + 4 <= o1; e += 4) {
        int s0 = srcs[e], s1 = srcs[e + 1], s2 = srcs[e + 2], s3 = srcs[e + 3];
        float2 v0 = __bfloat1622float2(*reinterpret_cast<const __nv_bfloat162*>(xsrc + (size_t)s0 * D + 2 * t));
        float2 v1 = __bfloat1622float2(*reinterpret_cast<const __nv_bfloat162*>(xsrc + (size_t)s1 * D + 2 * t));
        float2 v2 = __bfloat1622float2(*reinterpret_cast<const __nv_bfloat162*>(xsrc + (size_t)s2 * D + 2 * t));
        float2 v3 = __bfloat1622float2(*reinterpret_cast<const __nv_bfloat162*>(xsrc + (size_t)s3 * D + 2 * t));
        ax0 += v0.x; ay0 += v0.y;
        ax1 += v1.x; ay1 += v1.y;
        ax2 += v2.x; ay2 += v2.y;
        ax3 += v3.x; ay3 += v3.y;
    }
    for (; e < o1; e++) {
        float2 v = __bfloat1622float2(*reinterpret_cast<const __nv_bfloat162*>(xsrc + (size_t)srcs[e] * D + 2 * t));
        ax0 += v.x; ay0 += v.y;
    }
    float sx = (ax0 + ax1) + (ax2 + ax3);
    float sy = (ay0 + ay1) + (ay2 + ay3);
    float inv = (o1 > o0) ? 1.f / (float)(o1 - o0) : 0.f;
    float2 o = make_float2(sx * inv, sy * inv);
    reinterpret_cast<float2*>(g_msgs + (size_t)r * NN * D + (size_t)row * D)[t] = o;
}

// ---------------------------------------------------------------------------
// Segmented TF32 GEMM + fused leaky-ReLU + LayerNorm (+ bf16 shadow write).
// BM=128, BN=128, BK=32, 8 warps; warp tile = 16 rows x 128 cols.
// Smem tiles row-major with conflict-free padding (A: 36 wd/row, B: 136 wd/row).
// ---------------------------------------------------------------------------
__device__ __forceinline__ uint32_t f2tf32(float f) {
    uint32_t u;
    asm("cvt.rna.tf32.f32 %0, %1;" : "=r"(u) : "f"(f));
    return u;
}

__device__ __forceinline__ void mma_tf32(float* d, const uint32_t* a, const uint32_t* b) {
    asm volatile(
        "mma.sync.aligned.m16n8k8.row.col.f32.tf32.tf32.f32 "
        "{%0,%1,%2,%3}, {%4,%5,%6,%7}, {%8,%9}, {%0,%1,%2,%3};"
        : "+f"(d[0]), "+f"(d[1]), "+f"(d[2]), "+f"(d[3])
        : "r"(a[0]), "r"(a[1]), "r"(a[2]), "r"(a[3]), "r"(b[0]), "r"(b[1]));
}

#define APAD 36
#define BPAD 136

template <int SEGK, bool WRITEBF>
__global__ void __launch_bounds__(256) k_gemm_ln(const float* __restrict__ xin,
                                                const float* __restrict__ Wl,
                                                const float* __restrict__ gam,
                                                const float* __restrict__ bet,
                                                float* __restrict__ out) {
    __shared__ uint32_t sA[128 * APAD];
    __shared__ uint32_t sB[32 * BPAD];

    int tid = threadIdx.x;
    int lane = tid & 31;
    int w = tid >> 5;                 // warp 0..7 -> rows w*16..w*16+15
    int type = blockIdx.y;
    int r0 = blockIdx.x * 128;

    float acc[16][4];
    #pragma unroll
    for (int nt = 0; nt < 16; nt++)
        #pragma unroll
        for (int j = 0; j < 4; j++) acc[nt][j] = 0.f;

    int nseg = c_nseg[type];
    for (int seg = 0; seg < nseg; seg++) {
        int rel = c_segrel[type][seg];
        const float* Abase = (seg == 0) ? xin + (size_t)type * NN * SEGK
                                        : g_msgs + (size_t)rel * NN * SEGK;
        const float* Bbase = (seg == 0) ? g_wrc + (size_t)type * SEGK * HH
                                        : Wl + (size_t)rel * SEGK * HH;
        #pragma unroll
        for (int off = 0; off < SEGK; off += 32) {
            __syncthreads();
            // stage A (128 x 32), coalesced, conflict-free
            #pragma unroll
            for (int l = 0; l < 4; l++) {
                int f = tid + l * 256;          // float4 index 0..1023
                int row = f >> 3;
                int c0 = (f & 7) * 4;
                float4 v = make_float4(0.f, 0.f, 0.f, 0.f);
                if (r0 + row < NN)
                    v = *reinterpret_cast<const float4*>(
                        Abase + (size_t)(r0 + row) * SEGK + off + c0);
                uint4 u;
                u.x = f2tf32(v.x); u.y = f2tf32(v.y);
                u.z = f2tf32(v.z); u.w = f2tf32(v.w);
                *reinterpret_cast<uint4*>(&sA[row * APAD + c0]) = u;
            }
            // stage B (32 x 128), coalesced, conflict-free
            #pragma unroll
            for (int l = 0; l < 4; l++) {
                int f = tid + l * 256;
                int krow = f >> 5;
                int n0 = (f & 31) * 4;
                float4 v = *reinterpret_cast<const float4*>(
                    Bbase + (size_t)(off + krow) * HH + n0);
                uint4 u;
                u.x = f2tf32(v.x); u.y = f2tf32(v.y);
                u.z = f2tf32(v.z); u.w = f2tf32(v.w);
                *reinterpret_cast<uint4*>(&sB[krow * BPAD + n0]) = u;
            }
            __syncthreads();
            #pragma unroll
            for (int kt = 0; kt < 4; kt++) {
                int abase = (w * 16 + (lane >> 2)) * APAD + kt * 8 + (lane & 3);
                uint32_t af[4];
                af[0] = sA[abase];
                af[1] = sA[abase + 8 * APAD];
                af[2] = sA[abase + 4];
                af[3] = sA[abase + 8 * APAD + 4];
                int bb = (kt * 8 + (lane & 3)) * BPAD + (lane >> 2);
                #pragma unroll
                for (int nt = 0; nt < 16; nt++) {
                    uint32_t bf[2];
                    bf[0] = sB[bb + nt * 8];
                    bf[1] = sB[bb + nt * 8 + 4 * BPAD];
                    mma_tf32(acc[nt], af, bf);
                }
            }
        }
    }

    // ---- fused epilogue: bias, relation-mean, leaky ReLU, LayerNorm ----
    float inv = c_invcnt[type];
    #pragma unroll
    for (int h = 0; h < 2; h++) {
        int row = r0 + w * 16 + (lane >> 2) + h * 8;
        float v[16][2];
        float s = 0.f;
        #pragma unroll
        for (int nt = 0; nt < 16; nt++) {
            int col = nt * 8 + (lane & 3) * 2;
            float x0 = (acc[nt][2 * h] + g_bc[type * HH + col]) * inv;
            float x1 = (acc[nt][2 * h + 1] + g_bc[type * HH + col + 1]) * inv;
            x0 = (x0 >= 0.f) ? x0 : 0.01f * x0;
            x1 = (x1 >= 0.f) ? x1 : 0.01f * x1;
            v[nt][0] = x0; v[nt][1] = x1;
            s += x0 + x1;
        }
        s += __shfl_xor_sync(0xffffffffu, s, 1);
        s += __shfl_xor_sync(0xffffffffu, s, 2);
        float mu = s * (1.f / HH);
        float q = 0.f;
        #pragma unroll
        for (int nt = 0; nt < 16; nt++) {
            float d0 = v[nt][0] - mu, d1 = v[nt][1] - mu;
            v[nt][0] = d0; v[nt][1] = d1;
            q += d0 * d0 + d1 * d1;
        }
        q += __shfl_xor_sync(0xffffffffu, q, 1);
        q += __shfl_xor_sync(0xffffffffu, q, 2);
        float rs = rsqrtf(q * (1.f / HH) + 1e-5f);
        if (row < NN) {
            float* op = out + (size_t)type * NN * HH + (size_t)row * HH;
            __nv_bfloat16* obf = g_xbf + (size_t)type * NN * HH + (size_t)row * HH;
            #pragma unroll
            for (int nt = 0; nt < 16; nt++) {
                int col = nt * 8 + (lane & 3) * 2;
                float2 o;
                o.x = v[nt][0] * rs * gam[col] + bet[col];
                o.y = v[nt][1] * rs * gam[col + 1] + bet[col + 1];
                *reinterpret_cast<float2*>(op + col) = o;
                if (WRITEBF)
                    *reinterpret_cast<__nv_bfloat162*>(obf + col) =
                        __floats2bfloat162_rn(o.x, o.y);
            }
        }
    }
}

// ---------------------------------------------------------------------------
// Final: concat(9 types) @ Wfc + bfc, sigmoid
// ---------------------------------------------------------------------------
__device__ __forceinline__ float blockSum128(float v, float* sh) {
    #pragma unroll
    for (int o = 16; o > 0; o >>= 1) v += __shfl_xor_sync(0xffffffffu, v, o);
    int w = threadIdx.x >> 5;
    if ((threadIdx.x & 31) == 0) sh[w] = v;
    __syncthreads();
    float tot = sh[0] + sh[1] + sh[2] + sh[3];
    __syncthreads();
    return tot;
}

__global__ void k_final(const float* __restrict__ xs, const float* __restrict__ Wfc,
                        const float* __restrict__ bfc, float* __restrict__ out) {
    __shared__ float sh[4];
    int n = blockIdx.x;
    int t = threadIdx.x;
    float p = 0.f;
    #pragma unroll
    for (int i = 0; i < NT; i++)
        p += xs[((size_t)i * NN + n) * HH + t] * Wfc[i * HH + t];
    float tot = blockSum128(p, sh);
    if (t == 0) out[n] = 1.f / (1.f + expf(-(tot + bfc[0])));
}

// ---------------------------------------------------------------------------
// Host driver
// ---------------------------------------------------------------------------
template <int SEGK, bool WBF>
static void run_layer(const float* xin, const float* Wl, const float* Wr,
                      const float* b, const float* gam, const float* bet,
                      float* out) {
    constexpr int ROWS = 256 / SEGK;             // rows per agg block
    dim3 ga(NN / ROWS, NREL);
    dim3 ba(SEGK / 2, ROWS);
    k_agg_bf<SEGK><<<ga, ba>>>();
    k_combW<SEGK><<<(NT * SEGK * HH + 255) / 256, 256>>>(Wr);
    k_combB<<<(NT * HH + 255) / 256, 256>>>(b);
    dim3 gg((NN + 127) / 128, NT);
    k_gemm_ln<SEGK, WBF><<<gg, 256>>>(xin, Wl, gam, bet, out);
}

extern "C" void kernel_launch(void* const* d_in, const int* in_sizes, int n_in,
                              void* d_out, int out_size) {
    const float* x    = (const float*)d_in[0];
    const int* edges  = (const int*)d_in[1];
    const float* Wl1  = (const float*)d_in[2];
    const float* Wr1  = (const float*)d_in[3];
    const float* b1   = (const float*)d_in[4];
    const float* Wl2  = (const float*)d_in[5];
    const float* Wr2  = (const float*)d_in[6];
    const float* b2   = (const float*)d_in[7];
    const float* Wl3  = (const float*)d_in[8];
    const float* Wr3  = (const float*)d_in[9];
    const float* b3   = (const float*)d_in[10];
    const float* g1   = (const float*)d_in[11];
    const float* be1  = (const float*)d_in[12];
    const float* g2   = (const float*)d_in[13];
    const float* be2  = (const float*)d_in[14];
    const float* g3   = (const float*)d_in[15];
    const float* be3  = (const float*)d_in[16];
    const float* Wfc  = (const float*)d_in[17];
    const float* bfc  = (const float*)d_in[18];
    float* out = (float*)d_out;

    float *p_xs0, *p_xs1;
    cudaGetSymbolAddress((void**)&p_xs0, g_xs0);
    cudaGetSymbolAddress((void**)&p_xs1, g_xs1);

    k_cvt_zero<<<(NT * NN * DIN / 2 + 255) / 256, 256>>>(x);
    k_hist<<<(NREL * NE + 255) / 256, 256>>>(edges);
    k_scan<<<NREL, 1024>>>();
    k_fill<<<(NREL * NE + 255) / 256, 256>>>(edges);

    run_layer<DIN, true>(x,     Wl1, Wr1, b1, g1, be1, p_xs0);
    run_layer<HH,  true>(p_xs0, Wl2, Wr2, b2, g2, be2, p_xs1);
    run_layer<HH, false>(p_xs1, Wl3, Wr3, b3, g3, be3, p_xs0);

    k_final<<<NN, HH>>>(p_xs0, Wfc, bfc, out);
}